// round 16
// baseline (speedup 1.0000x reference)
#include <cuda_runtime.h>
#include <stdint.h>

#define NEGF (-1e30f)

constexpr int T = 1024;
constexpr int B = 32;
constexpr int C = 96;
constexpr int W = 16;   // beam width
constexpr int P = 4;    // top paths
constexpr int S = 21;   // top lp columns kept per (b,t); staircase needs i <= 20

// per (b,t): top-S non-blank lp columns as packed keys (ord(lp)<<7 | (127-c)), desc
__device__ unsigned long long g_sorted[(size_t)B * T * S];

// ---------- key helpers ----------
__device__ __forceinline__ unsigned ford(float f) {
    unsigned u = __float_as_uint(f);
    return (u & 0x80000000u) ? ~u : (u | 0x80000000u);
}
__device__ __forceinline__ float funord(unsigned ord) {
    unsigned u = (ord & 0x80000000u) ? (ord ^ 0x80000000u) : ~ord;
    return __uint_as_float(u);
}
// Payload-packed key: [54:23]=ord(score) [22:12]=2047-idx [11]=is_stay
// [10:7]=parent [6:0]=csym.  Higher score wins; ties -> lower idx wins
// (matches jax.lax.top_k); payload bits unreachable for distinct candidates.
__device__ __forceinline__ unsigned long long pack_key(
    float f, int idx, int is_stay, int parent, int csym) {
    return ((unsigned long long)ford(f) << 23)
         | ((unsigned long long)(2047 - idx) << 12)
         | ((unsigned long long)is_stay << 11)
         | ((unsigned long long)parent << 7)
         | (unsigned long long)csym;
}
__device__ __forceinline__ float key_score(unsigned long long k) {
    return funord((unsigned)(k >> 23));
}

__device__ __forceinline__ float lae(float a, float b) {   // jnp.logaddexp
    float m = fmaxf(a, b);
    float d = fabsf(a - b);
    return m + log1pf(expf(-d));
}

// descending bitonic sort of 32 keys across a warp (lane = index)
__device__ __forceinline__ void sort32_desc(unsigned long long& v, int lane) {
    #pragma unroll
    for (int k2 = 2; k2 <= 32; k2 <<= 1) {
        #pragma unroll
        for (int j = k2 >> 1; j > 0; j >>= 1) {
            unsigned long long o = __shfl_xor_sync(0xffffffffu, v, j);
            bool takemax = ((lane & k2) == 0) == ((lane & j) == 0);
            bool bigger  = v > o;
            v = (takemax == bigger) ? v : o;
        }
    }
}

// descending bitonic sort of 16 keys in each half-warp (10 passes)
__device__ __forceinline__ void sort16_desc_halves(unsigned long long& v, int l15) {
    #pragma unroll
    for (int k2 = 2; k2 <= 16; k2 <<= 1) {
        #pragma unroll
        for (int j = k2 >> 1; j > 0; j >>= 1) {
            unsigned long long o = __shfl_xor_sync(0xffffffffu, v, j);
            bool takemax = ((l15 & k2) == 0) == ((l15 & j) == 0);
            bool bigger  = v > o;
            v = (takemax == bigger) ? v : o;
        }
    }
}

// ============================================================================
// Kernel 1: per-(b,t) bitonic sort of non-blank lp columns, keep top-S.
// ============================================================================
__global__ __launch_bounds__(256)
void presort_kernel(const float* __restrict__ data)   // [T, B, C]
{
    int warp = (blockIdx.x * blockDim.x + threadIdx.x) >> 5;
    if (warp >= B * T) return;
    int b = warp / T, t = warp - b * T;
    int lane = threadIdx.x & 31;

    const float* row = data + ((size_t)t * B + b) * C;
    unsigned long long k[4];
    #pragma unroll
    for (int r = 0; r < 4; ++r) {
        int c = r * 32 + lane;
        if (c >= 1 && c < C)
            k[r] = ((unsigned long long)ford(row[c]) << 7) | (unsigned long long)(127 - c);
        else
            k[r] = 0ULL;
    }
    #pragma unroll
    for (int k2 = 2; k2 <= 128; k2 <<= 1) {
        #pragma unroll
        for (int j = 64; j > 0; j >>= 1) {
            if (j >= k2) continue;
            if (j >= 32) {
                int rj = j >> 5;
                #pragma unroll
                for (int r = 0; r < 4; ++r) {
                    if ((r & rj) == 0) {
                        int pr = r | rj;
                        bool desc = (((r * 32) & k2) == 0);
                        unsigned long long a = k[r], c2 = k[pr];
                        unsigned long long mx = a > c2 ? a : c2;
                        unsigned long long mn = a > c2 ? c2 : a;
                        k[r]  = desc ? mx : mn;
                        k[pr] = desc ? mn : mx;
                    }
                }
            } else {
                #pragma unroll
                for (int r = 0; r < 4; ++r) {
                    unsigned long long o = __shfl_xor_sync(0xffffffffu, k[r], j);
                    int e = r * 32 + lane;
                    bool takemax = ((e & k2) == 0) == ((lane & j) == 0);
                    bool bigger  = k[r] > o;
                    k[r] = (takemax == bigger) ? k[r] : o;
                }
            }
        }
    }
    if (lane < S)
        g_sorted[((size_t)b * T + t) * S + lane] = k[0];
}

// ============================================================================
// Kernel 2: 4 warps per batch element, ONE barrier/step, packed dual-merge,
// in-place demotion. HYBRID: warps 0-2 build step-(t+1) keys fused off the
// merged winners f (short chain, no transcendental); warp 3 keeps its R13
// pre-barrier stay build so the lae stays parallel to the sort32s.
// ============================================================================
__global__ __launch_bounds__(128, 1)
void ctc_beam_kernel(const float* __restrict__ data,      // [T, B, C]
                     const int*   __restrict__ data_len,  // [B]
                     float*       __restrict__ out)
{
    const int b    = blockIdx.x;
    const int tid  = threadIdx.x;
    const int lane = tid & 31;
    const int l15  = lane & 15;
    const int wid  = tid >> 5;
    const int len  = data_len[b];
    const unsigned FULL = 0xffffffffu;

    __shared__ unsigned long long s_top[2][4][32];  // [parity][warp][lane]
    __shared__ unsigned short s_bp[T + 1][W];       // row T = scrap (never read)
    __shared__ int   s_selslot[P], s_sellen[P];
    __shared__ float s_selscore[P];

    // staircase map for warps 0-2: slot s = wid*32+lane -> (w, i), i <= 20/(w+1)
    // row counts {21,11,7,6,5,4,3,3,3,3,2,2,2,2,2,2} -> 78 cells; slots 78+ dead
    int pw = -1, pi = 0;
    if (wid < 3) {
        const int pref[17] = {0,21,32,39,45,50,54,57,60,63,66,68,70,72,74,76,78};
        int s = wid * 32 + lane;
        #pragma unroll
        for (int ww = 0; ww < 16; ++ww)
            if (s >= pref[ww] && s < pref[ww + 1]) { pw = ww; pi = s - pref[ww]; }
    }
    const int pwm = pw & 15;
    const int idxc = W + pwm * C;                       // idx base, hoisted
    const int srt_lane = (lane < S) ? lane : (S - 1);   // clamped always-load

    // row 0 into registers (per warp; lane l holds cols l, l+32, l+64)
    float lp0r, lp1r, lp2r;
    unsigned long long srt_cur;
    {
        const float* row0 = data + (size_t)b * C;
        lp0r = row0[lane]; lp1r = row0[32 + lane]; lp2r = row0[64 + lane];
        srt_cur = g_sorted[((size_t)b * T) * S + srt_lane];
    }

    // replicated register beam state (lane = beam slot; high lanes never read)
    float pb   = (lane == 0) ? 0.0f : NEGF;
    float pnb  = NEGF;
    float ptot = lae(pb, pnb);
    int   llen = 0, llast = -1;

    // ---- prologue: warps 0-2 build t=0 ext keys (llast=-1: no demotion)
    unsigned long long k = 0ULL;
    if (wid < 3) {
        float pt = __shfl_sync(FULL, ptot, pwm);
        unsigned long long e = __shfl_sync(FULL, srt_cur, pi);
        int c = 127 - (int)(e & 127ULL);
        unsigned long long key =
            pack_key(funord((unsigned)(e >> 7)) + pt, idxc + c, 0, pwm, c);
        k = (pw >= 0) ? key : 0ULL;
    }

    for (int t = 0; t < len; ++t) {
        // prefetch row t+1 (consumed by fused build / next warp-3 build)
        const int tp1 = (t + 1 < T) ? (t + 1) : (T - 1);
        const float* rown = data + (size_t)(tp1 * B + b) * C;
        float n0 = rown[lane], n1 = rown[32 + lane], n2 = rown[64 + lane];
        unsigned long long nsrt = g_sorted[((size_t)b * T + tp1) * S + srt_lane];

        // ---- pre-barrier: warp 3 builds stays (R13 style, lae parallel to sorts)
        if (wid == 3) {
            float lp_blank3 = __shfl_sync(FULL, lp0r, 0);
            int ix3 = (llen > 0) ? llast : 0;
            ix3 = (ix3 < 0) ? 0 : ((ix3 > 95) ? 0 : ix3);
            float q0 = __shfl_sync(FULL, lp0r, ix3);
            float q1 = __shfl_sync(FULL, lp1r, ix3);
            float q2 = __shfl_sync(FULL, lp2r, ix3);
            float lpl3 = (ix3 < 32) ? q0 : ((ix3 < 64) ? q1 : q2);
            float spb3  = ptot + lp_blank3;
            float spnb3 = (llen > 0) ? (pnb + lpl3) : NEGF;
            unsigned long long staykey =
                pack_key(lae(spb3, spnb3), lane, 1, lane, 0);
            k = (lane < W) ? staykey : 0ULL;
            sort16_desc_halves(k, l15);      // 10 passes
        } else {
            sort32_desc(k, lane);            // 15 passes (keys from fused build)
        }
        s_top[t & 1][wid][lane] = k;
        __syncthreads();                     // the ONE barrier per step

        // ---- spb/spnb from OLD state + row t lp (overlaps merge)
        float lp_blank = __shfl_sync(FULL, lp0r, 0);
        int ix = (llen > 0) ? llast : 0;
        ix = (ix < 0) ? 0 : ((ix > 95) ? 0 : ix);
        float g0 = __shfl_sync(FULL, lp0r, ix);
        float g1 = __shfl_sync(FULL, lp1r, ix);
        float g2 = __shfl_sync(FULL, lp2r, ix);
        float lpl = (ix < 32) ? g0 : ((ix < 64) ? g1 : g2);
        float spb  = ptot + lp_blank;
        float spnb = (llen > 0) ? (pnb + lpl) : NEGF;

        // ---- packed dual-merge with reversed-LDS mirror (9 shuffle passes)
        const int half2 = (lane >> 4) << 1;              // 0 or 2
        unsigned long long a  = s_top[t & 1][half2][l15];
        unsigned long long bm = s_top[t & 1][half2 + 1][15 - l15];
        unsigned long long v = (a > bm) ? a : bm;
        #pragma unroll
        for (int j = 8; j > 0; j >>= 1) {
            unsigned long long o = __shfl_xor_sync(FULL, v, j);
            bool takemax = ((lane & j) == 0);
            bool bigger  = v > o;
            v = (takemax == bigger) ? v : o;
        }
        unsigned long long bm2 = __shfl_xor_sync(FULL, v, 31);
        unsigned long long f = (v > bm2) ? v : bm2;
        #pragma unroll
        for (int j = 8; j > 0; j >>= 1) {
            unsigned long long o = __shfl_xor_sync(FULL, f, j);
            bool takemax = ((lane & j) == 0);
            bool bigger  = f > o;
            f = (takemax == bigger) ? f : o;
        }
        // f: lanes 0-15 hold rank-lane winner (lanes 16-31 garbage, never read)

        // ---- FUSED ext build for warps 0-2: step-(t+1) keys straight from f
        if (wid < 3) {
            unsigned long long fq = __shfl_sync(FULL, f, pwm);
            float ptn   = key_score(fq);
            bool  st_q  = ((fq >> 11) & 1ULL) != 0ULL;
            int   par_q = (int)((fq >> 7) & 15ULL);
            int   cs_q  = (int)(fq & 127ULL);
            float sspb = __shfl_sync(FULL, spb,   par_q);
            int   sll  = __shfl_sync(FULL, llast, par_q);
            float pbn = st_q ? sspb : NEGF;
            int   lwn = st_q ? sll  : cs_q;
            unsigned long long e = __shfl_sync(FULL, nsrt, pi);
            int c = 127 - (int)(e & 127ULL);
            float base = (c == lwn) ? pbn : ptn;     // demoted cell = rep cand
            unsigned long long key =
                pack_key(funord((unsigned)(e >> 7)) + base, idxc + c, 0, pwm, c);
            k = (pw >= 0) ? key : 0ULL;
        }

        // ---- own-lane decode + parent gathers + state update (off crit. path
        //      for warps 0-2; paces warp 3's next stay build)
        float score   = key_score(f);
        bool  is_stay = ((f >> 11) & 1ULL) != 0ULL;
        int   parent  = (int)((f >> 7) & 15ULL);
        int   csym    = (int)(f & 127ULL);
        float p_spb  = __shfl_sync(FULL, spb,   parent);
        float p_spnb = __shfl_sync(FULL, spnb,  parent);
        int   p_len  = __shfl_sync(FULL, llen,  parent);
        int   p_last = __shfl_sync(FULL, llast, parent);

        pb    = is_stay ? p_spb  : NEGF;
        pnb   = is_stay ? p_spnb : score;
        ptot  = score;
        llen  = p_len + (is_stay ? 0 : 1);
        llast = is_stay ? p_last : csym;

        // branchless backpointer store: warp0 lanes 0-15 -> row t, rest -> scrap
        {
            int rowi = (wid == 0 && lane < W) ? t : T;
            s_bp[rowi][l15] =
                (unsigned short)((parent << 8) | (is_stay ? 0xFF : csym));
        }

        // rotate lp/srt registers (warp-private)
        lp0r = n0; lp1r = n1; lp2r = n2; srt_cur = nsrt;
    }

    // ---- final top-P over total beam probabilities (warp 0)
    if (wid == 0) {
        unsigned long long key = (lane < W)
            ? pack_key(ptot, lane, 0, lane, 0) : 0ULL;
        #pragma unroll
        for (int r = 0; r < P; ++r) {
            unsigned long long v = key;
            #pragma unroll
            for (int o = 16; o; o >>= 1) {
                unsigned long long w2 = __shfl_xor_sync(FULL, v, o);
                v = (w2 > v) ? w2 : v;
            }
            if (key == v) key = 0ULL;
            int slot = (int)((v >> 7) & 15ULL);
            int sl = __shfl_sync(FULL, llen, slot);
            if (lane == 0) {
                s_selslot[r]  = slot;
                s_selscore[r] = key_score(v);
                s_sellen[r]   = sl;
            }
        }
    }
    __syncthreads();

    // ---- outputs (flattened float32): -scores, lens, labels
    float* o_neg = out;
    float* o_len = out + B * P;
    float* o_dec = out + 2 * B * P;

    if (tid < P) {
        o_neg[b * P + tid] = -s_selscore[tid];
        o_len[b * P + tid] = (float)s_sellen[tid];
    }
    for (int i = tid; i < P * T; i += 128)
        o_dec[(size_t)b * P * T + i] = -1.0f;
    __syncthreads();

    if (tid < P) {
        int slot = s_selslot[tid];
        int pos  = s_sellen[tid];
        float* dst = o_dec + ((size_t)b * P + tid) * T;
        for (int tt = len - 1; tt >= 0; --tt) {
            unsigned e = s_bp[tt][slot];
            int sym = e & 0xFF;
            slot    = e >> 8;
            if (sym != 0xFF) dst[--pos] = (float)sym;
        }
    }
}

extern "C" void kernel_launch(void* const* d_in, const int* in_sizes, int n_in,
                              void* d_out, int out_size) {
    const float* data = (const float*)d_in[0];
    const int*   dlen = (const int*)d_in[1];
    presort_kernel<<<(B * T + 7) / 8, 256>>>(data);
    ctc_beam_kernel<<<B, 128>>>(data, dlen, (float*)d_out);
}

// round 17
// speedup vs baseline: 1.0654x; 1.0654x over previous
#include <cuda_runtime.h>
#include <stdint.h>

#define NEGF (-1e30f)

constexpr int T = 1024;
constexpr int B = 32;
constexpr int C = 96;
constexpr int W = 16;   // beam width
constexpr int P = 4;    // top paths
constexpr int S = 21;   // top lp columns kept per (b,t); staircase needs i <= 20

// per (b,t): top-S non-blank lp columns as packed keys (ord(lp)<<7 | (127-c)), desc
__device__ unsigned long long g_sorted[(size_t)B * T * S];

// ---------- key helpers ----------
__device__ __forceinline__ unsigned ford(float f) {
    unsigned u = __float_as_uint(f);
    return (u & 0x80000000u) ? ~u : (u | 0x80000000u);
}
__device__ __forceinline__ float funord(unsigned ord) {
    unsigned u = (ord & 0x80000000u) ? (ord ^ 0x80000000u) : ~ord;
    return __uint_as_float(u);
}
// Payload-packed key: [54:23]=ord(score) [22:12]=2047-idx [11]=is_stay
// [10:7]=parent [6:0]=csym.  Higher score wins; ties -> lower idx wins
// (matches jax.lax.top_k); payload bits unreachable for distinct candidates.
__device__ __forceinline__ unsigned long long pack_key(
    float f, int idx, int is_stay, int parent, int csym) {
    return ((unsigned long long)ford(f) << 23)
         | ((unsigned long long)(2047 - idx) << 12)
         | ((unsigned long long)is_stay << 11)
         | ((unsigned long long)parent << 7)
         | (unsigned long long)csym;
}
__device__ __forceinline__ float key_score(unsigned long long k) {
    return funord((unsigned)(k >> 23));
}

__device__ __forceinline__ float lae(float a, float b) {   // jnp.logaddexp
    float m = fmaxf(a, b);
    float d = fabsf(a - b);
    return m + log1pf(expf(-d));
}

// descending bitonic sort of 32 keys across a warp (lane = index)
__device__ __forceinline__ void sort32_desc(unsigned long long& v, int lane) {
    #pragma unroll
    for (int k2 = 2; k2 <= 32; k2 <<= 1) {
        #pragma unroll
        for (int j = k2 >> 1; j > 0; j >>= 1) {
            unsigned long long o = __shfl_xor_sync(0xffffffffu, v, j);
            bool takemax = ((lane & k2) == 0) == ((lane & j) == 0);
            bool bigger  = v > o;
            v = (takemax == bigger) ? v : o;
        }
    }
}

// descending bitonic sort of 16 keys in each half-warp (10 passes)
__device__ __forceinline__ void sort16_desc_halves(unsigned long long& v, int l15) {
    #pragma unroll
    for (int k2 = 2; k2 <= 16; k2 <<= 1) {
        #pragma unroll
        for (int j = k2 >> 1; j > 0; j >>= 1) {
            unsigned long long o = __shfl_xor_sync(0xffffffffu, v, j);
            bool takemax = ((l15 & k2) == 0) == ((l15 & j) == 0);
            bool bigger  = v > o;
            v = (takemax == bigger) ? v : o;
        }
    }
}

// ============================================================================
// Kernel 1: per-(b,t) bitonic sort of non-blank lp columns, keep top-S.
// ============================================================================
__global__ __launch_bounds__(256)
void presort_kernel(const float* __restrict__ data)   // [T, B, C]
{
    int warp = (blockIdx.x * blockDim.x + threadIdx.x) >> 5;
    if (warp >= B * T) return;
    int b = warp / T, t = warp - b * T;
    int lane = threadIdx.x & 31;

    const float* row = data + ((size_t)t * B + b) * C;
    unsigned long long k[4];
    #pragma unroll
    for (int r = 0; r < 4; ++r) {
        int c = r * 32 + lane;
        if (c >= 1 && c < C)
            k[r] = ((unsigned long long)ford(row[c]) << 7) | (unsigned long long)(127 - c);
        else
            k[r] = 0ULL;
    }
    #pragma unroll
    for (int k2 = 2; k2 <= 128; k2 <<= 1) {
        #pragma unroll
        for (int j = 64; j > 0; j >>= 1) {
            if (j >= k2) continue;
            if (j >= 32) {
                int rj = j >> 5;
                #pragma unroll
                for (int r = 0; r < 4; ++r) {
                    if ((r & rj) == 0) {
                        int pr = r | rj;
                        bool desc = (((r * 32) & k2) == 0);
                        unsigned long long a = k[r], c2 = k[pr];
                        unsigned long long mx = a > c2 ? a : c2;
                        unsigned long long mn = a > c2 ? c2 : a;
                        k[r]  = desc ? mx : mn;
                        k[pr] = desc ? mn : mx;
                    }
                }
            } else {
                #pragma unroll
                for (int r = 0; r < 4; ++r) {
                    unsigned long long o = __shfl_xor_sync(0xffffffffu, k[r], j);
                    int e = r * 32 + lane;
                    bool takemax = ((e & k2) == 0) == ((lane & j) == 0);
                    bool bigger  = k[r] > o;
                    k[r] = (takemax == bigger) ? k[r] : o;
                }
            }
        }
    }
    if (lane < S)
        g_sorted[((size_t)b * T + t) * S + lane] = k[0];
}

// ============================================================================
// Kernel 2: R13 structure (empirical optimum): 4 warps per batch element, ONE
// barrier/step, packed dual-merge, in-place demotion, warp 3 = stays with
// sort16. Trims: select-free spnb (NEGF absorbs exactly), IMNMX ix clamp,
// single-compare backpointer row select.
// ============================================================================
__global__ __launch_bounds__(128, 1)
void ctc_beam_kernel(const float* __restrict__ data,      // [T, B, C]
                     const int*   __restrict__ data_len,  // [B]
                     float*       __restrict__ out)
{
    const int b    = blockIdx.x;
    const int tid  = threadIdx.x;
    const int lane = tid & 31;
    const int l15  = lane & 15;
    const int wid  = tid >> 5;
    const int len  = data_len[b];
    const unsigned FULL = 0xffffffffu;

    __shared__ unsigned long long s_top[2][4][32];  // [parity][warp][lane]
    __shared__ unsigned short s_bp[T + 1][W];       // row T = scrap (never read)
    __shared__ int   s_selslot[P], s_sellen[P];
    __shared__ float s_selscore[P];

    // staircase map for warps 0-2: slot s = wid*32+lane -> (w, i), i <= 20/(w+1)
    // row counts {21,11,7,6,5,4,3,3,3,3,2,2,2,2,2,2} -> 78 cells; slots 78+ dead
    int pw = -1, pi = 0;
    if (wid < 3) {
        const int pref[17] = {0,21,32,39,45,50,54,57,60,63,66,68,70,72,74,76,78};
        int s = wid * 32 + lane;
        #pragma unroll
        for (int ww = 0; ww < 16; ++ww)
            if (s >= pref[ww] && s < pref[ww + 1]) { pw = ww; pi = s - pref[ww]; }
    }
    const int pwm = pw & 15;
    const int idxc = W + pwm * C;                       // idx base, hoisted
    const int srt_lane = (lane < S) ? lane : (S - 1);   // clamped always-load

    // row 0 into registers (per warp; lane l holds cols l, l+32, l+64)
    float lp0r, lp1r, lp2r;
    unsigned long long srt_cur;
    {
        const float* row0 = data + (size_t)b * C;
        lp0r = row0[lane]; lp1r = row0[32 + lane]; lp2r = row0[64 + lane];
        srt_cur = g_sorted[((size_t)b * T) * S + srt_lane];
    }

    // replicated register beam state (lane = beam slot; high lanes never read)
    float pb   = (lane == 0) ? 0.0f : NEGF;
    float pnb  = NEGF;
    float ptot = lae(pb, pnb);
    int   llen = 0, llast = -1;

    for (int t = 0; t < len; ++t) {
        // prefetch row t+1 (branchless clamp)
        const int tp1 = (t + 1 < T) ? (t + 1) : (T - 1);
        const float* rown = data + (size_t)(tp1 * B + b) * C;
        float n0 = rown[lane], n1 = rown[32 + lane], n2 = rown[64 + lane];
        unsigned long long nsrt = g_sorted[((size_t)b * T + tp1) * S + srt_lane];

        // ---- pool build + per-warp sort
        unsigned long long k;
        if (wid == 3) {
            // warp 3: ONLY the 16 stay candidates (needs the lae)
            float lp_blank = __shfl_sync(FULL, lp0r, 0);
            int ix3 = (llast > 0) ? llast : 0;           // IMNMX-style clamp
            float q0 = __shfl_sync(FULL, lp0r, ix3);
            float q1 = __shfl_sync(FULL, lp1r, ix3);
            float q2 = __shfl_sync(FULL, lp2r, ix3);
            float lpl3 = (ix3 < 32) ? q0 : ((ix3 < 64) ? q1 : q2);
            float spb3  = ptot + lp_blank;
            float spnb3 = pnb + lpl3;        // pnb == -1e30 exactly when dead
            unsigned long long staykey =
                pack_key(lae(spb3, spnb3), lane, 1, lane, 0);
            k = (lane < W) ? staykey : 0ULL;
            sort16_desc_halves(k, l15);      // 10 passes; lanes 0-15 sorted desc
        } else {
            // warps 0-2: staircase ext cells with IN-PLACE demotion
            float pt  = __shfl_sync(FULL, ptot,  pwm);
            float pbw = __shfl_sync(FULL, pb,    pwm);
            int   lw  = __shfl_sync(FULL, llast, pwm);
            unsigned long long e = __shfl_sync(FULL, srt_cur, pi);
            int c = 127 - (int)(e & 127ULL);
            float base = (c == lw) ? pbw : pt;   // demoted cell = rep candidate
            unsigned long long key =
                pack_key(funord((unsigned)(e >> 7)) + base, idxc + c, 0, pwm, c);
            k = (pw >= 0) ? key : 0ULL;
            sort32_desc(k, lane);                // 15 passes
        }
        s_top[t & 1][wid][lane] = k;             // all 32 lanes: no divergence
        __syncthreads();                         // the ONE barrier per step

        // ---- stay/rep probabilities for the update (overlaps merge below)
        float lp_blank = __shfl_sync(FULL, lp0r, 0);
        int ix = (llast > 0) ? llast : 0;
        float g0 = __shfl_sync(FULL, lp0r, ix);
        float g1 = __shfl_sync(FULL, lp1r, ix);
        float g2 = __shfl_sync(FULL, lp2r, ix);
        float lpl = (ix < 32) ? g0 : ((ix < 64) ? g1 : g2);
        float spb  = ptot + lp_blank;
        float spnb = pnb + lpl;                  // exact: NEGF absorbs
        // ---- packed dual-merge with reversed-LDS mirror (9 shuffle passes)
        const int half2 = (lane >> 4) << 1;               // 0 or 2
        unsigned long long a  = s_top[t & 1][half2][l15];
        unsigned long long bm = s_top[t & 1][half2 + 1][15 - l15];  // mirrored load
        unsigned long long v = (a > bm) ? a : bm;
        #pragma unroll
        for (int j = 8; j > 0; j >>= 1) {                 // clean within halves
            unsigned long long o = __shfl_xor_sync(FULL, v, j);
            bool takemax = ((lane & j) == 0);
            bool bigger  = v > o;
            v = (takemax == bigger) ? v : o;
        }
        // final merge: m01 (lanes 0-15) vs m23 (lanes 16-31), mirror = lane^31
        unsigned long long bm2 = __shfl_xor_sync(FULL, v, 31);
        unsigned long long f = (v > bm2) ? v : bm2;
        #pragma unroll
        for (int j = 8; j > 0; j >>= 1) {
            unsigned long long o = __shfl_xor_sync(FULL, f, j);
            bool takemax = ((lane & j) == 0);
            bool bigger  = f > o;
            f = (takemax == bigger) ? f : o;
        }
        // f: lanes 0-15 hold rank-lane winner (lanes 16-31 garbage, never read)

        // ---- state update: payload decode, NO divide
        float score   = key_score(f);
        bool  is_stay = ((f >> 11) & 1ULL) != 0ULL;
        int   parent  = (int)((f >> 7) & 15ULL);
        int   csym    = (int)(f & 127ULL);
        float p_spb  = __shfl_sync(FULL, spb,   parent);
        float p_spnb = __shfl_sync(FULL, spnb,  parent);
        int   p_len  = __shfl_sync(FULL, llen,  parent);
        int   p_last = __shfl_sync(FULL, llast, parent);

        pb    = is_stay ? p_spb  : NEGF;
        pnb   = is_stay ? p_spnb : score;
        ptot  = score;
        llen  = p_len + (is_stay ? 0 : 1);
        llast = is_stay ? p_last : csym;

        // branchless backpointer store: tid 0-15 -> row t, others -> scrap row
        {
            int rowi = (tid < W) ? t : T;
            s_bp[rowi][l15] =
                (unsigned short)((parent << 8) | (is_stay ? 0xFF : csym));
        }

        // rotate lp/srt registers (warp-private)
        lp0r = n0; lp1r = n1; lp2r = n2; srt_cur = nsrt;
    }

    // ---- final top-P over total beam probabilities (warp 0)
    if (wid == 0) {
        unsigned long long key = (lane < W)
            ? pack_key(ptot, lane, 0, lane, 0) : 0ULL;
        #pragma unroll
        for (int r = 0; r < P; ++r) {
            unsigned long long v = key;
            #pragma unroll
            for (int o = 16; o; o >>= 1) {
                unsigned long long w2 = __shfl_xor_sync(FULL, v, o);
                v = (w2 > v) ? w2 : v;
            }
            if (key == v) key = 0ULL;
            int slot = (int)((v >> 7) & 15ULL);
            int sl = __shfl_sync(FULL, llen, slot);
            if (lane == 0) {
                s_selslot[r]  = slot;
                s_selscore[r] = key_score(v);
                s_sellen[r]   = sl;
            }
        }
    }
    __syncthreads();

    // ---- outputs (flattened float32): -scores, lens, labels
    float* o_neg = out;
    float* o_len = out + B * P;
    float* o_dec = out + 2 * B * P;

    if (tid < P) {
        o_neg[b * P + tid] = -s_selscore[tid];
        o_len[b * P + tid] = (float)s_sellen[tid];
    }
    for (int i = tid; i < P * T; i += 128)
        o_dec[(size_t)b * P * T + i] = -1.0f;
    __syncthreads();

    if (tid < P) {
        int slot = s_selslot[tid];
        int pos  = s_sellen[tid];
        float* dst = o_dec + ((size_t)b * P + tid) * T;
        for (int tt = len - 1; tt >= 0; --tt) {
            unsigned e = s_bp[tt][slot];
            int sym = e & 0xFF;
            slot    = e >> 8;
            if (sym != 0xFF) dst[--pos] = (float)sym;
        }
    }
}

extern "C" void kernel_launch(void* const* d_in, const int* in_sizes, int n_in,
                              void* d_out, int out_size) {
    const float* data = (const float*)d_in[0];
    const int*   dlen = (const int*)d_in[1];
    presort_kernel<<<(B * T + 7) / 8, 256>>>(data);
    ctc_beam_kernel<<<B, 128>>>(data, dlen, (float*)d_out);
}